// round 3
// baseline (speedup 1.0000x reference)
#include <cuda_runtime.h>
#include <cuda_bf16.h>

// ---------------------------------------------------------------------------
// ResAdd_ws_dist: AdderNet bottleneck block forward.
//   out[0:802816]  = relu(bn3(adder_c3(h2)) + relu(bnds(adder_ds(x))))
//   out[802816]    = sum of 4 KL divergences (if out_size > 802816)
// All adder layers: out = -sum |patch - w|  (L1 "convolution", zero padding
// contributes |0 - w| terms).  BN in training mode (batch stats, biased var).
// ---------------------------------------------------------------------------

#define BATCH 4
#define HW 784          // 28*28
#define NPIX (BATCH*HW) // 3136

struct Scratch {
    float f_ds[32768];
    float f_c1[8192];
    float f_c2[36864];
    float f_c3[16384];
    float kl[4];
    float buf_ds[802816];   // adder_ds output (pre-bn)
    float buf_c3[802816];   // adder_c3 output (pre-bn)
    float buf_c1[200704];   // adder_c1 output
    float buf_peg[200704];  // PEG depthwise output (pre-bn1)
    float buf_h1[200704];   // relu(bn1(peg))
    float buf_c2[200704];   // adder_c2 output (pre-bn2)
    float buf_h2[200704];   // relu(bn2(c2))
    float st1[128];         // bn1: mean[64], istd[64]
    float st2[128];         // bn2
    float st3[512];         // bn3: mean[256], istd[256]
    float stds[512];        // bnds
};
__device__ Scratch g_s;

// ---------------- block reductions (blockDim == 256) ----------------
__device__ __forceinline__ float br_sum(float v, float* red) {
    int tid = threadIdx.x;
    red[tid] = v; __syncthreads();
    for (int s = 128; s > 0; s >>= 1) {
        if (tid < s) red[tid] += red[tid + s];
        __syncthreads();
    }
    float r = red[0]; __syncthreads();
    return r;
}
__device__ __forceinline__ float br_min(float v, float* red) {
    int tid = threadIdx.x;
    red[tid] = v; __syncthreads();
    for (int s = 128; s > 0; s >>= 1) {
        if (tid < s) red[tid] = fminf(red[tid], red[tid + s]);
        __syncthreads();
    }
    float r = red[0]; __syncthreads();
    return r;
}
__device__ __forceinline__ float br_max(float v, float* red) {
    int tid = threadIdx.x;
    red[tid] = v; __syncthreads();
    for (int s = 128; s > 0; s >>= 1) {
        if (tid < s) red[tid] = fmaxf(red[tid], red[tid + s]);
        __syncthreads();
    }
    float r = red[0]; __syncthreads();
    return r;
}

// ---------------- weight bin-reconstruct + KL (one block per tensor) -------
__global__ void weights_kl_kernel(
    const float* __restrict__ w0, const float* __restrict__ w1,
    const float* __restrict__ w2, const float* __restrict__ w3,
    const float* __restrict__ a0, const float* __restrict__ a1,
    const float* __restrict__ a2, const float* __restrict__ a3,
    const float* __restrict__ l0, const float* __restrict__ l1,
    const float* __restrict__ l2, const float* __restrict__ l3,
    float* __restrict__ f0, float* __restrict__ f1,
    float* __restrict__ f2, float* __restrict__ f3,
    float* __restrict__ kl_out)
{
    __shared__ float red[256];
    int t = blockIdx.x;
    const float* w   = (t==0)?w0:(t==1)?w1:(t==2)?w2:w3;
    const float* aff = (t==0)?a0:(t==1)?a1:(t==2)?a2:a3;
    const float* lap = (t==0)?l0:(t==1)?l1:(t==2)?l2:l3;
    float*       f   = (t==0)?f0:(t==1)?f1:(t==2)?f2:f3;
    const int    n   = (t==0)?32768:(t==1)?8192:(t==2)?36864:16384;
    int tid = threadIdx.x;

    // phase A: min/max of w
    float mn = 3.4e38f, mx = -3.4e38f;
    for (int i = tid; i < n; i += 256) {
        float v = w[i];
        mn = fminf(mn, v); mx = fmaxf(mx, v);
    }
    float wmin = br_min(mn, red);
    float wmax = br_max(mx, red);
    float range = wmax - wmin;

    // phase B: reconstruct f = w * affine[bin] * (bin < 100); track maxes
    float mf = -3.4e38f, ml = -3.4e38f;
    for (int i = tid; i < n; i += 256) {
        float v = w[i];
        float tt = (v - wmin) / range;        // same FP sequence as reference
        int idx = (int)floorf(tt * 100.0f);
        float val = (idx < 100) ? v * aff[idx] : 0.0f;
        f[i] = val;
        mf = fmaxf(mf, val);
        ml = fmaxf(ml, lap[i]);
    }
    float maxf = br_max(mf, red);
    float maxl = br_max(ml, red);

    // phase C: logsumexp pieces + sum p*(lap - f)
    float ef = 0.f, el = 0.f, spl = 0.f;
    for (int i = tid; i < n; i += 256) {
        float fv = f[i], lv = lap[i];
        ef += expf(fv - maxf);
        float e = expf(lv - maxl);
        el += e;
        spl += e * (lv - fv);
    }
    float efT  = br_sum(ef,  red);
    float elT  = br_sum(el,  red);
    float splT = br_sum(spl, red);
    if (tid == 0) {
        float lse_f = maxf + logf(efT);
        float lse_l = maxl + logf(elT);
        kl_out[t] = (splT / elT + lse_f - lse_l) / (float)n;
    }
}

// ---------------- 1x1 adder layer ------------------------------------------
// block: 256 threads = 64 pixels x 4 output-groups; each thread does 8 outputs.
// grid: (ceil(784/64)=13, Cout/32, BATCH). Weights tile (32 x CIN) in SMEM.
template<int CIN>
__global__ void adder1x1_kernel(const float* __restrict__ in,
                                const float* __restrict__ w,
                                float* __restrict__ out, int Cout)
{
    __shared__ float ws[32 * CIN];
    int b  = blockIdx.z;
    int o0 = blockIdx.y * 32;
    int p0 = blockIdx.x * 64;
    for (int i = threadIdx.x; i < 32 * CIN; i += 256)
        ws[i] = w[o0 * CIN + i];
    __syncthreads();

    int px = threadIdx.x & 63;
    int og = threadIdx.x >> 6;       // 0..3 -> outputs og*8..og*8+7
    int p  = p0 + px;
    if (p >= HW) return;

    const float* xp = in + (long)b * CIN * HW + p;
    const float* wp = ws + og * 8 * CIN;
    float acc[8] = {0,0,0,0,0,0,0,0};
    #pragma unroll 4
    for (int c = 0; c < CIN; ++c) {
        float xv = xp[c * HW];
        #pragma unroll
        for (int k = 0; k < 8; ++k)
            acc[k] += fabsf(xv - wp[k * CIN + c]);
    }
    int ob = o0 + og * 8;
    #pragma unroll
    for (int k = 0; k < 8; ++k)
        out[((long)b * Cout + ob + k) * HW + p] = -acc[k];
}

// ---------------- 3x3 adder layer (64->64, pad 1) --------------------------
// block: 128 threads = 64 pixels x 2 output-groups; each thread 8 outputs.
// grid: (13, 4, BATCH). Weight tile 16 x (64*9) in SMEM (36 KB).
__global__ void adder3x3_kernel(const float* __restrict__ in,
                                const float* __restrict__ w,
                                float* __restrict__ out)
{
    __shared__ float ws[16 * 576];
    int b  = blockIdx.z;
    int o0 = blockIdx.y * 16;
    int p0 = blockIdx.x * 64;
    for (int i = threadIdx.x; i < 16 * 576; i += 128)
        ws[i] = w[o0 * 576 + i];
    __syncthreads();

    int px = threadIdx.x & 63;
    int og = threadIdx.x >> 6;       // 0..1
    int p  = p0 + px;
    if (p >= HW) return;
    int y = p / 28, x = p - y * 28;

    int  off[9];
    bool vld[9];
    #pragma unroll
    for (int t = 0; t < 9; ++t) {
        int dy = t / 3 - 1, dx = t % 3 - 1;
        int yy = y + dy, xx = x + dx;
        vld[t] = (yy >= 0 && yy < 28 && xx >= 0 && xx < 28);
        off[t] = yy * 28 + xx;
    }

    const float* wb = ws + og * 8 * 576;
    float acc[8] = {0,0,0,0,0,0,0,0};
    for (int c = 0; c < 64; ++c) {
        const float* ip = in + ((long)b * 64 + c) * HW;
        const float* wc = wb + c * 9;
        #pragma unroll
        for (int t = 0; t < 9; ++t) {
            float v = vld[t] ? ip[off[t]] : 0.0f;   // zero padding IS included
            #pragma unroll
            for (int k = 0; k < 8; ++k)
                acc[k] += fabsf(v - wc[k * 576 + t]);
        }
    }
    int ob = o0 + og * 8;
    #pragma unroll
    for (int k = 0; k < 8; ++k)
        out[((long)b * 64 + ob + k) * HW + p] = -acc[k];
}

// ---------------- PEG depthwise 3x3 (pad 1) --------------------------------
__global__ void peg_kernel(const float* __restrict__ in,
                           const float* __restrict__ pw,
                           float* __restrict__ out)
{
    int idx = blockIdx.x * 256 + threadIdx.x;
    if (idx >= 200704) return;
    int p  = idx % HW;
    int ch = (idx / HW) & 63;
    int b  = idx / (HW * 64);
    int y = p / 28, x = p - y * 28;
    const float* wc = pw + ch * 9;
    const float* ip = in + ((long)b * 64 + ch) * HW;
    float acc = 0.f;
    #pragma unroll
    for (int t = 0; t < 9; ++t) {
        int yy = y + t / 3 - 1, xx = x + t % 3 - 1;
        float v = (yy >= 0 && yy < 28 && xx >= 0 && xx < 28) ? ip[yy * 28 + xx] : 0.0f;
        acc += fabsf(v - wc[t]);
    }
    out[idx] = -acc;
}

// ---------------- BN batch stats: one block per channel, two-pass ----------
__global__ void bn_stats_kernel(const float* __restrict__ in,
                                float* __restrict__ stats, int C)
{
    __shared__ float red[256];
    int ch = blockIdx.x, tid = threadIdx.x;
    float s = 0.f;
    for (int i = tid; i < NPIX; i += 256) {
        int b = i / HW, p = i - b * HW;
        s += in[((long)b * C + ch) * HW + p];
    }
    float mean = br_sum(s, red) * (1.0f / NPIX);
    float s2 = 0.f;
    for (int i = tid; i < NPIX; i += 256) {
        int b = i / HW, p = i - b * HW;
        float d = in[((long)b * C + ch) * HW + p] - mean;
        s2 += d * d;
    }
    float var = br_sum(s2, red) * (1.0f / NPIX);
    if (tid == 0) {
        stats[ch]     = mean;
        stats[C + ch] = rsqrtf(var + 1e-5f);
    }
}

// ---------------- bn + relu elementwise ------------------------------------
__global__ void bn_apply_relu_kernel(const float* __restrict__ in,
                                     const float* __restrict__ stats,
                                     const float* __restrict__ g,
                                     const float* __restrict__ bta,
                                     float* __restrict__ out, int C, int n)
{
    int idx = blockIdx.x * 256 + threadIdx.x;
    if (idx >= n) return;
    int ch = (idx / HW) % C;
    float v = (in[idx] - stats[ch]) * stats[C + ch] * g[ch] + bta[ch];
    out[idx] = fmaxf(v, 0.0f);
}

// ---------------- fused epilogue: relu(bn3(c3) + relu(bnds(ds))) + KL ------
__global__ void final_kernel(const float* __restrict__ c3,
                             const float* __restrict__ ds,
                             const float* __restrict__ st3,
                             const float* __restrict__ stds,
                             const float* __restrict__ g3, const float* __restrict__ b3,
                             const float* __restrict__ gds, const float* __restrict__ bds,
                             const float* __restrict__ kl,
                             float* __restrict__ out, int out_size)
{
    int idx = blockIdx.x * 256 + threadIdx.x;
    if (idx == 0 && out_size > 802816)
        out[802816] = kl[0] + kl[1] + kl[2] + kl[3];
    if (idx >= 802816) return;
    int ch = (idx / HW) & 255;
    float v3  = (c3[idx] - st3[ch])  * st3[256 + ch]  * g3[ch]  + b3[ch];
    float vds = fmaxf((ds[idx] - stds[ch]) * stds[256 + ch] * gds[ch] + bds[ch], 0.0f);
    out[idx] = fmaxf(v3 + vds, 0.0f);
}

// ---------------------------------------------------------------------------
extern "C" void kernel_launch(void* const* d_in, const int* in_sizes, int n_in,
                              void* d_out, int out_size)
{
    const float* x    = (const float*)d_in[0];
    const float* w_ds = (const float*)d_in[1];
    const float* w_c1 = (const float*)d_in[2];
    const float* w_c2 = (const float*)d_in[3];
    const float* w_c3 = (const float*)d_in[4];
    const float* a_ds = (const float*)d_in[5];
    const float* a_c1 = (const float*)d_in[6];
    const float* a_c2 = (const float*)d_in[7];
    const float* a_c3 = (const float*)d_in[8];
    const float* pegw = (const float*)d_in[9];
    const float* g1   = (const float*)d_in[10];
    const float* b1   = (const float*)d_in[11];
    const float* g2   = (const float*)d_in[12];
    const float* b2   = (const float*)d_in[13];
    const float* g3   = (const float*)d_in[14];
    const float* b3   = (const float*)d_in[15];
    const float* gds  = (const float*)d_in[16];
    const float* bds  = (const float*)d_in[17];
    const float* lds  = (const float*)d_in[18];
    const float* lc1  = (const float*)d_in[19];
    const float* lc2  = (const float*)d_in[20];
    const float* lc3  = (const float*)d_in[21];
    float* out = (float*)d_out;

    Scratch* s = nullptr;
    cudaGetSymbolAddress((void**)&s, g_s);

    // 1) bin-reconstruct all 4 weight tensors + their KL terms
    weights_kl_kernel<<<4, 256>>>(w_ds, w_c1, w_c2, w_c3,
                                  a_ds, a_c1, a_c2, a_c3,
                                  lds, lc1, lc2, lc3,
                                  s->f_ds, s->f_c1, s->f_c2, s->f_c3, s->kl);

    // 2) downsample branch + conv1 (both read x; independent)
    adder1x1_kernel<128><<<dim3(13, 8, BATCH), 256>>>(x, s->f_ds, s->buf_ds, 256);
    adder1x1_kernel<128><<<dim3(13, 2, BATCH), 256>>>(x, s->f_c1, s->buf_c1, 64);

    // 3) PEG depthwise on raw conv1 output, then bn1+relu
    peg_kernel<<<784, 256>>>(s->buf_c1, pegw, s->buf_peg);
    bn_stats_kernel<<<64, 256>>>(s->buf_peg, s->st1, 64);
    bn_apply_relu_kernel<<<784, 256>>>(s->buf_peg, s->st1, g1, b1, s->buf_h1, 64, 200704);

    // 4) conv2 3x3 + bn2 + relu
    adder3x3_kernel<<<dim3(13, 4, BATCH), 128>>>(s->buf_h1, s->f_c2, s->buf_c2);
    bn_stats_kernel<<<64, 256>>>(s->buf_c2, s->st2, 64);
    bn_apply_relu_kernel<<<784, 256>>>(s->buf_c2, s->st2, g2, b2, s->buf_h2, 64, 200704);

    // 5) conv3 1x1
    adder1x1_kernel<64><<<dim3(13, 8, BATCH), 256>>>(s->buf_h2, s->f_c3, s->buf_c3, 256);

    // 6) bn3 & bnds stats, fused epilogue (+ KL scalar)
    bn_stats_kernel<<<256, 256>>>(s->buf_c3, s->st3, 256);
    bn_stats_kernel<<<256, 256>>>(s->buf_ds, s->stds, 256);
    final_kernel<<<3136, 256>>>(s->buf_c3, s->buf_ds, s->st3, s->stds,
                                g3, b3, gds, bds, s->kl, out, out_size);
}

// round 4
// speedup vs baseline: 1.8351x; 1.8351x over previous
#include <cuda_runtime.h>
#include <cuda_bf16.h>

typedef unsigned long long ULL;

#define HW 784
#define NPIX 3136

// ---------------------------------------------------------------------------
// Scratch (all offsets multiple of 16 bytes; verified: floats before buffers
// total 386128 bytes = 24133*16)
// accd layout: sum_ds@0, ss_ds@256, sum2@512, ss2@576, sum3@640, ss3@896
// accf layout: ef[4]@0, el[4]@4, spl[4]@8
// ---------------------------------------------------------------------------
struct __align__(16) Scratch {
    float f_ds[32768], f_c1[8192], f_c2[36864], f_c3[16384];
    float wmin[4], range[4];
    double accd[1152];
    float accf[12];
    float buf_ds[802816], buf_c3[802816];
    float buf_c1[200704], buf_h1[200704], buf_c2[200704];
};
__device__ Scratch g_s;

// ---------------- helpers --------------------------------------------------
__device__ __forceinline__ ULL addf2(ULL a, ULL b) {
    ULL r; asm("add.rn.f32x2 %0,%1,%2;" : "=l"(r) : "l"(a), "l"(b)); return r;
}
__device__ __forceinline__ ULL pack2(float v) {
    ULL r; unsigned u = __float_as_uint(v);
    asm("mov.b64 %0,{%1,%1};" : "=l"(r) : "r"(u)); return r;
}
#define ABS2_MASK 0x7FFFFFFF7FFFFFFFULL

__device__ __forceinline__ float br_sum256(float v, float* red) {
    int tid = threadIdx.x;
    red[tid] = v; __syncthreads();
    for (int s = 128; s > 0; s >>= 1) {
        if (tid < s) red[tid] += red[tid + s];
        __syncthreads();
    }
    float r = red[0]; __syncthreads();
    return r;
}

// ---------------- prep: zero accumulators + per-tensor min/max -------------
__global__ void __launch_bounds__(1024) prep_kernel(
    const float* __restrict__ w0, const float* __restrict__ w1,
    const float* __restrict__ w2, const float* __restrict__ w3)
{
    __shared__ float rmn[1024], rmx[1024];
    int tid = threadIdx.x, t = blockIdx.x;
    if (t == 0) {
        for (int i = tid; i < 1152; i += 1024) g_s.accd[i] = 0.0;
        if (tid < 12) g_s.accf[tid] = 0.f;
    }
    const float* w = (t==0)?w0:(t==1)?w1:(t==2)?w2:w3;
    int n = (t==0)?32768:(t==1)?8192:(t==2)?36864:16384;
    float mn = 3.4e38f, mx = -3.4e38f;
    for (int i = tid; i < n; i += 1024) {
        float v = w[i];
        mn = fminf(mn, v); mx = fmaxf(mx, v);
    }
    rmn[tid] = mn; rmx[tid] = mx; __syncthreads();
    for (int s = 512; s > 0; s >>= 1) {
        if (tid < s) {
            rmn[tid] = fminf(rmn[tid], rmn[tid + s]);
            rmx[tid] = fmaxf(rmx[tid], rmx[tid + s]);
        }
        __syncthreads();
    }
    if (tid == 0) { g_s.wmin[t] = rmn[0]; g_s.range[t] = rmx[0] - rmn[0]; }
}

// ---------------- reconstruct weights + KL partial sums --------------------
// 368 blocks x 256; boundaries 0/128/160/304 blocks (all tensor sizes %256==0)
__global__ void __launch_bounds__(256) recon_kernel(
    const float* __restrict__ w0, const float* __restrict__ w1,
    const float* __restrict__ w2, const float* __restrict__ w3,
    const float* __restrict__ a0, const float* __restrict__ a1,
    const float* __restrict__ a2, const float* __restrict__ a3,
    const float* __restrict__ l0, const float* __restrict__ l1,
    const float* __restrict__ l2, const float* __restrict__ l3)
{
    __shared__ float red[256];
    int bid = blockIdx.x, tid = threadIdx.x;
    int t, lb;
    if (bid < 128)      { t = 0; lb = bid; }
    else if (bid < 160) { t = 1; lb = bid - 128; }
    else if (bid < 304) { t = 2; lb = bid - 160; }
    else                { t = 3; lb = bid - 304; }
    const float *w, *aff, *lap; float* f;
    if (t == 0)      { w = w0; aff = a0; lap = l0; f = g_s.f_ds; }
    else if (t == 1) { w = w1; aff = a1; lap = l1; f = g_s.f_c1; }
    else if (t == 2) { w = w2; aff = a2; lap = l2; f = g_s.f_c2; }
    else             { w = w3; aff = a3; lap = l3; f = g_s.f_c3; }

    int i = lb * 256 + tid;
    float v = w[i];
    float tt = (v - g_s.wmin[t]) / g_s.range[t];   // same FP sequence as ref
    int idx = (int)floorf(tt * 100.0f);
    float val = (idx < 100) ? v * aff[idx] : 0.0f;
    f[i] = val;
    float lv = lap[i];
    float el_ = expf(lv);               // no max-subtraction needed: safe range
    float ef_ = expf(val);
    float spl_ = el_ * (lv - val);
    float sef  = br_sum256(ef_,  red);
    float sel  = br_sum256(el_,  red);
    float sspl = br_sum256(spl_, red);
    if (tid == 0) {
        atomicAdd(&g_s.accf[t],     sef);
        atomicAdd(&g_s.accf[4 + t], sel);
        atomicAdd(&g_s.accf[8 + t], sspl);
    }
}

// ---------------- 1x1 adder, f32x2 packed, optional inline-BN in / stats ---
// 256 thr = 64 px x 4 og; og handles 8 outputs (4 f32x2 pairs); tile 32 out.
template<int CIN, bool BN_IN, bool STATS>
__global__ void __launch_bounds__(256) adder1x1_kernel(
    const float* __restrict__ in, const float* __restrict__ wsrc,
    float* __restrict__ out, int Cout,
    const double* __restrict__ bsum, const double* __restrict__ bss,
    const float* __restrict__ bg, const float* __restrict__ bb,
    double* __restrict__ osum, double* __restrict__ oss)
{
    __shared__ ULL wsp[16 * CIN];
    __shared__ float scale[CIN], shift[CIN];
    int tid = threadIdx.x;
    int b = blockIdx.z, o0 = blockIdx.y * 32, p0 = blockIdx.x * 64;

    for (int j = tid; j < 16 * CIN; j += 256) {
        int pr = j / CIN, c = j - pr * CIN;
        float wA = wsrc[(o0 + 2 * pr) * CIN + c];
        float wB = wsrc[(o0 + 2 * pr + 1) * CIN + c];
        wsp[j] = ((ULL)__float_as_uint(-wB) << 32) | (ULL)__float_as_uint(-wA);
    }
    if (BN_IN) {
        if (tid < CIN) {
            double m = bsum[tid] * (1.0 / 3136.0);
            double var = bss[tid] * (1.0 / 3136.0) - m * m;
            float istd = rsqrtf((float)var + 1e-5f);
            float sc = istd * bg[tid];
            scale[tid] = sc;
            shift[tid] = bb[tid] - (float)m * sc;
        }
    }
    __syncthreads();

    int px = tid & 63, og = tid >> 6;
    int p = p0 + px;
    bool valid = p < HW;
    int pc = valid ? p : (HW - 1);

    const float* xp = in + (size_t)b * CIN * HW + pc;
    const ULL* wp = wsp + og * 4 * CIN;
    ULL acc[4] = {0ull, 0ull, 0ull, 0ull};

    #pragma unroll 2
    for (int c = 0; c < CIN; ++c) {
        float xv = xp[(size_t)c * HW];
        if (BN_IN) xv = fmaxf(fmaf(xv, scale[c], shift[c]), 0.0f);
        ULL xx = pack2(xv);
        #pragma unroll
        for (int kp = 0; kp < 4; ++kp) {
            ULL d = addf2(xx, wp[kp * CIN + c]) & ABS2_MASK;
            acc[kp] = addf2(acc[kp], d);
        }
    }

    float a[8];
    #pragma unroll
    for (int kp = 0; kp < 4; ++kp) {
        a[2 * kp]     = __uint_as_float((unsigned)acc[kp]);
        a[2 * kp + 1] = __uint_as_float((unsigned)(acc[kp] >> 32));
    }
    int ob = o0 + og * 8;
    if (valid) {
        #pragma unroll
        for (int k = 0; k < 8; ++k)
            out[((size_t)b * Cout + ob + k) * HW + p] = -a[k];
    }
    if (STATS) {
        #pragma unroll
        for (int k = 0; k < 8; ++k) {
            float s  = valid ? -a[k] : 0.0f;
            float s2 = valid ? a[k] * a[k] : 0.0f;
            for (int o = 16; o > 0; o >>= 1) {
                s  += __shfl_xor_sync(0xffffffffu, s,  o);
                s2 += __shfl_xor_sync(0xffffffffu, s2, o);
            }
            if ((tid & 31) == 0) {
                atomicAdd(&osum[ob + k], (double)s);
                atomicAdd(&oss[ob + k],  (double)s2);
            }
        }
    }
}

// ---------------- 3x3 adder (64->64, pad 1), f32x2 packed, + stats ---------
// 256 thr = 64 px x 4 og; og handles 4 outputs (2 pairs); tile 16 out.
// grid (13, 4, 4) = 208 blocks.
__global__ void __launch_bounds__(256) adder3x3_kernel(
    const float* __restrict__ in, const float* __restrict__ wsrc,
    float* __restrict__ out,
    double* __restrict__ osum, double* __restrict__ oss)
{
    __shared__ ULL wsp[8 * 576];   // 36 KB
    int tid = threadIdx.x;
    int b = blockIdx.z, o0 = blockIdx.y * 16, p0 = blockIdx.x * 64;

    for (int j = tid; j < 8 * 576; j += 256) {
        int pr = j / 576, r = j - pr * 576;
        float wA = wsrc[(o0 + 2 * pr) * 576 + r];
        float wB = wsrc[(o0 + 2 * pr + 1) * 576 + r];
        wsp[j] = ((ULL)__float_as_uint(-wB) << 32) | (ULL)__float_as_uint(-wA);
    }
    __syncthreads();

    int px = tid & 63, og = tid >> 6;
    int p = p0 + px;
    bool valid = p < HW;
    int pc = valid ? p : (HW - 1);
    int y = pc / 28, x = pc - y * 28;

    int off[9]; bool vld[9];
    #pragma unroll
    for (int t = 0; t < 9; ++t) {
        int yy = y + t / 3 - 1, xx = x + t % 3 - 1;
        vld[t] = (yy >= 0 && yy < 28 && xx >= 0 && xx < 28);
        off[t] = yy * 28 + xx;
    }

    const ULL* wp = wsp + og * 2 * 576;
    ULL acc[2] = {0ull, 0ull};

    for (int c = 0; c < 64; ++c) {
        const float* ip = in + ((size_t)(b * 64 + c)) * HW;
        float v[9];
        #pragma unroll
        for (int t = 0; t < 9; ++t) v[t] = vld[t] ? ip[off[t]] : 0.0f;
        #pragma unroll
        for (int t = 0; t < 9; ++t) {
            ULL xx2 = pack2(v[t]);
            #pragma unroll
            for (int kp = 0; kp < 2; ++kp) {
                ULL d = addf2(xx2, wp[kp * 576 + c * 9 + t]) & ABS2_MASK;
                acc[kp] = addf2(acc[kp], d);
            }
        }
    }

    float a[4];
    #pragma unroll
    for (int kp = 0; kp < 2; ++kp) {
        a[2 * kp]     = __uint_as_float((unsigned)acc[kp]);
        a[2 * kp + 1] = __uint_as_float((unsigned)(acc[kp] >> 32));
    }
    int ob = o0 + og * 4;
    if (valid) {
        #pragma unroll
        for (int k = 0; k < 4; ++k)
            out[((size_t)b * 64 + ob + k) * HW + p] = -a[k];
    }
    #pragma unroll
    for (int k = 0; k < 4; ++k) {
        float s  = valid ? -a[k] : 0.0f;
        float s2 = valid ? a[k] * a[k] : 0.0f;
        for (int o = 16; o > 0; o >>= 1) {
            s  += __shfl_xor_sync(0xffffffffu, s,  o);
            s2 += __shfl_xor_sync(0xffffffffu, s2, o);
        }
        if ((tid & 31) == 0) {
            atomicAdd(&osum[ob + k], (double)s);
            atomicAdd(&oss[ob + k],  (double)s2);
        }
    }
}

// ---------------- fused PEG depthwise 3x3 + bn1 stats + bn1/relu apply -----
// One block per channel; full channel (all 4 batches) in SMEM.
__global__ void __launch_bounds__(256) peg_fused_kernel(
    const float* __restrict__ in, const float* __restrict__ pw,
    const float* __restrict__ g1, const float* __restrict__ b1,
    float* __restrict__ out)
{
    __shared__ float inb[NPIX];
    __shared__ float ob[NPIX];
    __shared__ float red[256];
    int tid = threadIdx.x, ch = blockIdx.x;

    for (int bb = 0; bb < 4; ++bb)
        for (int p = tid; p < HW; p += 256)
            inb[bb * HW + p] = in[((size_t)(bb * 64 + ch)) * HW + p];
    __syncthreads();

    float wc[9];
    #pragma unroll
    for (int t = 0; t < 9; ++t) wc[t] = pw[ch * 9 + t];

    float ps = 0.f;
    for (int i = tid; i < NPIX; i += 256) {
        int bb = i / HW, p = i - bb * HW;
        int y = p / 28, x = p - y * 28;
        float acc = 0.f;
        #pragma unroll
        for (int t = 0; t < 9; ++t) {
            int yy = y + t / 3 - 1, xx = x + t % 3 - 1;
            float v = (yy >= 0 && yy < 28 && xx >= 0 && xx < 28)
                      ? inb[bb * HW + yy * 28 + xx] : 0.0f;
            acc += fabsf(v - wc[t]);
        }
        ob[i] = -acc;
        ps += -acc;
    }
    float mean = br_sum256(ps, red) * (1.0f / NPIX);
    float pss = 0.f;
    for (int i = tid; i < NPIX; i += 256) {
        float d = ob[i] - mean;
        pss += d * d;
    }
    float var = br_sum256(pss, red) * (1.0f / NPIX);
    float istd = rsqrtf(var + 1e-5f);
    float sc = istd * g1[ch], sh = b1[ch] - mean * sc;
    for (int i = tid; i < NPIX; i += 256) {
        int bb = i / HW, p = i - bb * HW;
        out[((size_t)(bb * 64 + ch)) * HW + p] = fmaxf(ob[i] * sc + sh, 0.0f);
    }
}

// ---------------- final: bn3/bnds from sums + residual add + relu + KL -----
__global__ void __launch_bounds__(256) final_kernel(
    const float* __restrict__ g3, const float* __restrict__ b3,
    const float* __restrict__ gds, const float* __restrict__ bds,
    float* __restrict__ out, int out_size)
{
    int idx4 = blockIdx.x * 256 + threadIdx.x;
    if (idx4 == 0 && out_size > 802816) {
        const float ns[4] = {32768.f, 8192.f, 36864.f, 16384.f};
        float kl = 0.f;
        #pragma unroll
        for (int t = 0; t < 4; ++t) {
            float ef = g_s.accf[t], el = g_s.accf[4 + t], spl = g_s.accf[8 + t];
            kl += (spl / el + logf(ef) - logf(el)) / ns[t];
        }
        out[802816] = kl;
    }
    size_t base = (size_t)idx4 * 4;
    int ch = (int)((base / HW) & 255);

    double m3d = g_s.accd[640 + ch] * (1.0 / 3136.0);
    double v3d = g_s.accd[896 + ch] * (1.0 / 3136.0) - m3d * m3d;
    float m3 = (float)m3d, istd3 = rsqrtf((float)v3d + 1e-5f);
    float sc3 = istd3 * g3[ch], sh3 = b3[ch] - m3 * sc3;

    double mdd = g_s.accd[0 + ch] * (1.0 / 3136.0);
    double vdd = g_s.accd[256 + ch] * (1.0 / 3136.0) - mdd * mdd;
    float md = (float)mdd, istdd = rsqrtf((float)vdd + 1e-5f);
    float scd = istdd * gds[ch], shd = bds[ch] - md * scd;

    float4 a = *(const float4*)(g_s.buf_c3 + base);
    float4 d = *(const float4*)(g_s.buf_ds + base);
    float4 o;
    o.x = fmaxf(fmaf(a.x, sc3, sh3) + fmaxf(fmaf(d.x, scd, shd), 0.f), 0.f);
    o.y = fmaxf(fmaf(a.y, sc3, sh3) + fmaxf(fmaf(d.y, scd, shd), 0.f), 0.f);
    o.z = fmaxf(fmaf(a.z, sc3, sh3) + fmaxf(fmaf(d.z, scd, shd), 0.f), 0.f);
    o.w = fmaxf(fmaf(a.w, sc3, sh3) + fmaxf(fmaf(d.w, scd, shd), 0.f), 0.f);
    *(float4*)(out + base) = o;
}

// ---------------------------------------------------------------------------
extern "C" void kernel_launch(void* const* d_in, const int* in_sizes, int n_in,
                              void* d_out, int out_size)
{
    const float* x    = (const float*)d_in[0];
    const float* w_ds = (const float*)d_in[1];
    const float* w_c1 = (const float*)d_in[2];
    const float* w_c2 = (const float*)d_in[3];
    const float* w_c3 = (const float*)d_in[4];
    const float* a_ds = (const float*)d_in[5];
    const float* a_c1 = (const float*)d_in[6];
    const float* a_c2 = (const float*)d_in[7];
    const float* a_c3 = (const float*)d_in[8];
    const float* pegw = (const float*)d_in[9];
    const float* g1   = (const float*)d_in[10];
    const float* b1   = (const float*)d_in[11];
    const float* g2   = (const float*)d_in[12];
    const float* b2   = (const float*)d_in[13];
    const float* g3   = (const float*)d_in[14];
    const float* b3   = (const float*)d_in[15];
    const float* gds  = (const float*)d_in[16];
    const float* bds  = (const float*)d_in[17];
    const float* lds  = (const float*)d_in[18];
    const float* lc1  = (const float*)d_in[19];
    const float* lc2  = (const float*)d_in[20];
    const float* lc3  = (const float*)d_in[21];
    float* out = (float*)d_out;

    Scratch* s = nullptr;
    cudaGetSymbolAddress((void**)&s, g_s);

    // 1) zero accumulators + per-tensor weight min/max
    prep_kernel<<<4, 1024>>>(w_ds, w_c1, w_c2, w_c3);

    // 2) bin-reconstruct all weights + KL partial sums (wide)
    recon_kernel<<<368, 256>>>(w_ds, w_c1, w_c2, w_c3,
                               a_ds, a_c1, a_c2, a_c3,
                               lds, lc1, lc2, lc3);

    // 3) downsample branch (+ bnds stats) and conv1 (no stats needed)
    adder1x1_kernel<128, false, true><<<dim3(13, 8, 4), 256>>>(
        x, s->f_ds, s->buf_ds, 256,
        nullptr, nullptr, nullptr, nullptr, s->accd + 0, s->accd + 256);
    adder1x1_kernel<128, false, false><<<dim3(13, 2, 4), 256>>>(
        x, s->f_c1, s->buf_c1, 64,
        nullptr, nullptr, nullptr, nullptr, nullptr, nullptr);

    // 4) PEG depthwise + bn1 stats + bn1/relu apply -> h1
    peg_fused_kernel<<<64, 256>>>(s->buf_c1, pegw, g1, b1, s->buf_h1);

    // 5) conv2 3x3 (+ bn2 stats)
    adder3x3_kernel<<<dim3(13, 4, 4), 256>>>(
        s->buf_h1, s->f_c2, s->buf_c2, s->accd + 512, s->accd + 576);

    // 6) conv3 1x1 with inline bn2+relu on input (+ bn3 stats)
    adder1x1_kernel<64, true, true><<<dim3(13, 8, 4), 256>>>(
        s->buf_c2, s->f_c3, s->buf_c3, 256,
        s->accd + 512, s->accd + 576, g2, b2, s->accd + 640, s->accd + 896);

    // 7) fused epilogue: bn3 + relu(bnds) residual + relu, and KL scalar
    final_kernel<<<784, 256>>>(g3, b3, gds, bds, out, out_size);
}

// round 5
// speedup vs baseline: 2.3192x; 1.2638x over previous
#include <cuda_runtime.h>
#include <cuda_bf16.h>

typedef unsigned long long ULL;

#define HW 784
#define NPIX 3136

// ---------------------------------------------------------------------------
// Scratch. accd layout: sum_ds@0, ss_ds@256, sum2@512, ss2@576, sum3@640,
// ss3@896.  accf: ef[4]@0, el[4]@4, spl[4]@8.
// ---------------------------------------------------------------------------
struct __align__(16) Scratch {
    float f_ds[32768], f_c1[8192], f_c2[36864], f_c3[16384];
    float wmin[4], range[4];
    double accd[1152];
    float accf[12];
    float buf_ds[802816], buf_c3[802816];
    float buf_c1[200704], buf_h1[200704], buf_c2[200704];
};
__device__ Scratch g_s;

// ---------------- helpers --------------------------------------------------
__device__ __forceinline__ ULL addf2(ULL a, ULL b) {
    ULL r; asm("add.rn.f32x2 %0,%1,%2;" : "=l"(r) : "l"(a), "l"(b)); return r;
}
__device__ __forceinline__ ULL pack2(float v) {
    ULL r; unsigned u = __float_as_uint(v);
    asm("mov.b64 %0,{%1,%1};" : "=l"(r) : "r"(u)); return r;
}
__device__ __forceinline__ ULL packAB(float a, float b) {
    return ((ULL)__float_as_uint(b) << 32) | (ULL)__float_as_uint(a);
}
#define ABS2_MASK 0x7FFFFFFF7FFFFFFFULL

template<int BS>
__device__ __forceinline__ float blk_sum(float v) {
    __shared__ float red[BS / 32];
    #pragma unroll
    for (int o = 16; o > 0; o >>= 1) v += __shfl_xor_sync(0xffffffffu, v, o);
    int w = threadIdx.x >> 5, l = threadIdx.x & 31;
    if (l == 0) red[w] = v;
    __syncthreads();
    if (w == 0) {
        float s = (l < BS / 32) ? red[l] : 0.f;
        #pragma unroll
        for (int o = 16; o > 0; o >>= 1) s += __shfl_xor_sync(0xffffffffu, s, o);
        if (l == 0) red[0] = s;
    }
    __syncthreads();
    float r = red[0];
    __syncthreads();
    return r;
}

// ---------------- prep: zero accumulators + per-tensor min/max -------------
__global__ void __launch_bounds__(1024) prep_kernel(
    const float* __restrict__ w0, const float* __restrict__ w1,
    const float* __restrict__ w2, const float* __restrict__ w3)
{
    __shared__ float rmn[32], rmx[32];
    int tid = threadIdx.x, t = blockIdx.x;
    if (t == 0) {
        for (int i = tid; i < 1152; i += 1024) g_s.accd[i] = 0.0;
        if (tid < 12) g_s.accf[tid] = 0.f;
    }
    const float* w = (t==0)?w0:(t==1)?w1:(t==2)?w2:w3;
    int n4 = ((t==0)?32768:(t==1)?8192:(t==2)?36864:16384) >> 2;
    float mn = 3.4e38f, mx = -3.4e38f;
    for (int i = tid; i < n4; i += 1024) {
        float4 v = ((const float4*)w)[i];
        mn = fminf(mn, fminf(fminf(v.x, v.y), fminf(v.z, v.w)));
        mx = fmaxf(mx, fmaxf(fmaxf(v.x, v.y), fmaxf(v.z, v.w)));
    }
    #pragma unroll
    for (int o = 16; o > 0; o >>= 1) {
        mn = fminf(mn, __shfl_xor_sync(0xffffffffu, mn, o));
        mx = fmaxf(mx, __shfl_xor_sync(0xffffffffu, mx, o));
    }
    int wi = tid >> 5, l = tid & 31;
    if (l == 0) { rmn[wi] = mn; rmx[wi] = mx; }
    __syncthreads();
    if (wi == 0) {
        mn = rmn[l]; mx = rmx[l];
        #pragma unroll
        for (int o = 16; o > 0; o >>= 1) {
            mn = fminf(mn, __shfl_xor_sync(0xffffffffu, mn, o));
            mx = fmaxf(mx, __shfl_xor_sync(0xffffffffu, mx, o));
        }
        if (l == 0) { g_s.wmin[t] = mn; g_s.range[t] = mx - mn; }
    }
}

// ---------------- reconstruct weights + KL partials (float4, 92 blocks) ----
__global__ void __launch_bounds__(256) recon_kernel(
    const float* __restrict__ w0, const float* __restrict__ w1,
    const float* __restrict__ w2, const float* __restrict__ w3,
    const float* __restrict__ a0, const float* __restrict__ a1,
    const float* __restrict__ a2, const float* __restrict__ a3,
    const float* __restrict__ l0, const float* __restrict__ l1,
    const float* __restrict__ l2, const float* __restrict__ l3)
{
    int bid = blockIdx.x, tid = threadIdx.x;
    int t, lb;
    if (bid < 32)      { t = 0; lb = bid; }
    else if (bid < 40) { t = 1; lb = bid - 32; }
    else if (bid < 76) { t = 2; lb = bid - 40; }
    else               { t = 3; lb = bid - 76; }
    const float *w, *aff, *lap; float* f;
    if (t == 0)      { w = w0; aff = a0; lap = l0; f = g_s.f_ds; }
    else if (t == 1) { w = w1; aff = a1; lap = l1; f = g_s.f_c1; }
    else if (t == 2) { w = w2; aff = a2; lap = l2; f = g_s.f_c2; }
    else             { w = w3; aff = a3; lap = l3; f = g_s.f_c3; }

    float wmin = g_s.wmin[t], range = g_s.range[t];
    int i4 = lb * 256 + tid;
    float4 v4 = ((const float4*)w)[i4];
    float4 l4 = ((const float4*)lap)[i4];
    float vv[4] = {v4.x, v4.y, v4.z, v4.w};
    float ll[4] = {l4.x, l4.y, l4.z, l4.w};
    float fo[4];
    float ef = 0.f, el = 0.f, spl = 0.f;
    #pragma unroll
    for (int k = 0; k < 4; ++k) {
        float v = vv[k];
        float tt = (v - wmin) / range;            // same FP sequence as ref
        int idx = (int)floorf(tt * 100.0f);
        float val = (idx < 100) ? v * aff[idx] : 0.0f;
        fo[k] = val;
        float e = expf(ll[k]);
        ef += expf(val);
        el += e;
        spl += e * (ll[k] - val);
    }
    ((float4*)f)[i4] = make_float4(fo[0], fo[1], fo[2], fo[3]);
    float sef  = blk_sum<256>(ef);
    float sel  = blk_sum<256>(el);
    float sspl = blk_sum<256>(spl);
    if (tid == 0) {
        atomicAdd(&g_s.accf[t],     sef);
        atomicAdd(&g_s.accf[4 + t], sel);
        atomicAdd(&g_s.accf[8 + t], sspl);
    }
}

// ---------------- generic 1x1 adder (f32x2, LDS.128 weights) ---------------
// 256 thr = 64 px x 4 og; each og handles 8 outputs (4 pairs).
// FUSED: blockIdx.y selects ds (y<8, stats) vs c1 (y>=8, no stats).
template<int CIN, bool FUSED, bool BN_IN, bool STATS_T>
__global__ void __launch_bounds__(256) adder1x1_kernel(
    const float* __restrict__ in, const float* __restrict__ wsrc_a,
    float* __restrict__ out_a, int Cout_a,
    const double* __restrict__ bsum, const double* __restrict__ bss,
    const float* __restrict__ bg, const float* __restrict__ bb,
    double* __restrict__ osum_a, double* __restrict__ oss_a)
{
    __shared__ __align__(16) ULL wq[16 * CIN];   // [og][c][pr]
    __shared__ float scale[CIN], shift[CIN];
    int tid = threadIdx.x;
    int b = blockIdx.z, yb = blockIdx.y;

    const float* wsrc; float* out; int Cout, o0; bool do_stats;
    double *osum, *oss;
    if (FUSED) {
        bool is_ds = yb < 8;
        wsrc = is_ds ? g_s.f_ds : g_s.f_c1;
        out  = is_ds ? g_s.buf_ds : g_s.buf_c1;
        Cout = is_ds ? 256 : 64;
        o0   = (is_ds ? yb : yb - 8) * 32;
        do_stats = is_ds;
        osum = g_s.accd; oss = g_s.accd + 256;
    } else {
        wsrc = wsrc_a; out = out_a; Cout = Cout_a; o0 = yb * 32;
        do_stats = STATS_T; osum = osum_a; oss = oss_a;
    }
    int p0 = blockIdx.x * 64;

    // build interleaved packed weights: wq[((og*CIN + c)*4) + pr]
    for (int j = tid; j < 16 * CIN; j += 256) {
        int og = j / (4 * CIN), r = j - og * 4 * CIN;
        int c = r >> 2, pr = r & 3;
        int o = o0 + og * 8 + 2 * pr;
        wq[j] = packAB(-wsrc[o * CIN + c], -wsrc[(o + 1) * CIN + c]);
    }
    if (BN_IN) {
        if (tid < CIN) {
            double m = bsum[tid] * (1.0 / 3136.0);
            double var = bss[tid] * (1.0 / 3136.0) - m * m;
            float istd = rsqrtf((float)var + 1e-5f);
            float sc = istd * bg[tid];
            scale[tid] = sc;
            shift[tid] = bb[tid] - (float)m * sc;
        }
        __syncthreads();
    } else {
        __syncthreads();
    }

    int px = tid & 63, og = tid >> 6;
    int p = p0 + px;
    bool valid = p < HW;
    int pc = valid ? p : (HW - 1);

    const float* xp = in + (size_t)b * CIN * HW + pc;
    const ULL* wp = wq + og * 4 * CIN;
    ULL acc0 = 0, acc1 = 0, acc2 = 0, acc3 = 0;

    #pragma unroll 4
    for (int c = 0; c < CIN; ++c) {
        float xv = xp[(size_t)c * HW];
        if (BN_IN) xv = fmaxf(fmaf(xv, scale[c], shift[c]), 0.0f);
        ULL xx = pack2(xv);
        ulonglong2 w01 = *(const ulonglong2*)(wp + c * 4);
        ulonglong2 w23 = *(const ulonglong2*)(wp + c * 4 + 2);
        acc0 = addf2(acc0, addf2(xx, w01.x) & ABS2_MASK);
        acc1 = addf2(acc1, addf2(xx, w01.y) & ABS2_MASK);
        acc2 = addf2(acc2, addf2(xx, w23.x) & ABS2_MASK);
        acc3 = addf2(acc3, addf2(xx, w23.y) & ABS2_MASK);
    }

    float a[8];
    a[0] = __uint_as_float((unsigned)acc0); a[1] = __uint_as_float((unsigned)(acc0 >> 32));
    a[2] = __uint_as_float((unsigned)acc1); a[3] = __uint_as_float((unsigned)(acc1 >> 32));
    a[4] = __uint_as_float((unsigned)acc2); a[5] = __uint_as_float((unsigned)(acc2 >> 32));
    a[6] = __uint_as_float((unsigned)acc3); a[7] = __uint_as_float((unsigned)(acc3 >> 32));
    int ob = o0 + og * 8;
    if (valid) {
        #pragma unroll
        for (int k = 0; k < 8; ++k)
            out[((size_t)b * Cout + ob + k) * HW + p] = -a[k];
    }
    if (do_stats) {
        #pragma unroll
        for (int k = 0; k < 8; ++k) {
            float s  = valid ? -a[k] : 0.0f;
            float s2 = valid ? a[k] * a[k] : 0.0f;
            #pragma unroll
            for (int o = 16; o > 0; o >>= 1) {
                s  += __shfl_xor_sync(0xffffffffu, s,  o);
                s2 += __shfl_xor_sync(0xffffffffu, s2, o);
            }
            if ((tid & 31) == 0) {
                atomicAdd(&osum[ob + k], (double)s);
                atomicAdd(&oss[ob + k],  (double)s2);
            }
        }
    }
}

// ---------------- 3x3 adder (64->64, pad 1), interleaved packed weights ----
// 256 thr = 64 px x 4 og; og handles 4 outputs (2 pairs). grid (13,4,4).
__global__ void __launch_bounds__(256) adder3x3_kernel(
    const float* __restrict__ in, const float* __restrict__ wsrc,
    float* __restrict__ out,
    double* __restrict__ osum, double* __restrict__ oss)
{
    __shared__ __align__(16) ULL wq[4608];   // [og][ct][kp], 36 KB
    int tid = threadIdx.x;
    int b = blockIdx.z, o0 = blockIdx.y * 16, p0 = blockIdx.x * 64;

    for (int j = tid; j < 4608; j += 256) {
        int og = j / 1152, r = j - og * 1152;
        int ct = r >> 1, kp = r & 1;
        int o = o0 + og * 4 + 2 * kp;
        wq[j] = packAB(-wsrc[o * 576 + ct], -wsrc[(o + 1) * 576 + ct]);
    }
    __syncthreads();

    int px = tid & 63, og = tid >> 6;
    int p = p0 + px;
    bool valid = p < HW;
    int pc = valid ? p : (HW - 1);
    int y = pc / 28, x = pc - y * 28;

    int off[9]; bool vld[9];
    #pragma unroll
    for (int t = 0; t < 9; ++t) {
        int yy = y + t / 3 - 1, xx = x + t % 3 - 1;
        vld[t] = (yy >= 0 && yy < 28 && xx >= 0 && xx < 28);
        off[t] = yy * 28 + xx;
    }

    const ulonglong2* wp = (const ulonglong2*)(wq + og * 1152);
    ULL acc0 = 0, acc1 = 0;

    for (int c = 0; c < 64; ++c) {
        const float* ip = in + ((size_t)(b * 64 + c)) * HW;
        float v[9];
        #pragma unroll
        for (int t = 0; t < 9; ++t) v[t] = vld[t] ? ip[off[t]] : 0.0f;
        const ulonglong2* wc = wp + c * 9;
        #pragma unroll
        for (int t = 0; t < 9; ++t) {
            ULL xx2 = pack2(v[t]);
            ulonglong2 ww = wc[t];
            acc0 = addf2(acc0, addf2(xx2, ww.x) & ABS2_MASK);
            acc1 = addf2(acc1, addf2(xx2, ww.y) & ABS2_MASK);
        }
    }

    float a[4];
    a[0] = __uint_as_float((unsigned)acc0); a[1] = __uint_as_float((unsigned)(acc0 >> 32));
    a[2] = __uint_as_float((unsigned)acc1); a[3] = __uint_as_float((unsigned)(acc1 >> 32));
    int ob = o0 + og * 4;
    if (valid) {
        #pragma unroll
        for (int k = 0; k < 4; ++k)
            out[((size_t)b * 64 + ob + k) * HW + p] = -a[k];
    }
    #pragma unroll
    for (int k = 0; k < 4; ++k) {
        float s  = valid ? -a[k] : 0.0f;
        float s2 = valid ? a[k] * a[k] : 0.0f;
        #pragma unroll
        for (int o = 16; o > 0; o >>= 1) {
            s  += __shfl_xor_sync(0xffffffffu, s,  o);
            s2 += __shfl_xor_sync(0xffffffffu, s2, o);
        }
        if ((tid & 31) == 0) {
            atomicAdd(&osum[ob + k], (double)s);
            atomicAdd(&oss[ob + k],  (double)s2);
        }
    }
}

// ---------------- fused PEG depthwise 3x3 + bn1 stats + bn1/relu apply -----
__global__ void __launch_bounds__(512) peg_fused_kernel(
    const float* __restrict__ in, const float* __restrict__ pw,
    const float* __restrict__ g1, const float* __restrict__ b1,
    float* __restrict__ out)
{
    __shared__ float inb[NPIX];
    __shared__ float ob[NPIX];
    int tid = threadIdx.x, ch = blockIdx.x;

    for (int bb = 0; bb < 4; ++bb)
        for (int p = tid; p < HW; p += 512)
            inb[bb * HW + p] = in[((size_t)(bb * 64 + ch)) * HW + p];
    __syncthreads();

    float wc[9];
    #pragma unroll
    for (int t = 0; t < 9; ++t) wc[t] = pw[ch * 9 + t];

    float ps = 0.f;
    for (int i = tid; i < NPIX; i += 512) {
        int bb = i / HW, p = i - bb * HW;
        int y = p / 28, x = p - y * 28;
        float acc = 0.f;
        #pragma unroll
        for (int t = 0; t < 9; ++t) {
            int yy = y + t / 3 - 1, xx = x + t % 3 - 1;
            float v = (yy >= 0 && yy < 28 && xx >= 0 && xx < 28)
                      ? inb[bb * HW + yy * 28 + xx] : 0.0f;
            acc += fabsf(v - wc[t]);
        }
        ob[i] = -acc;
        ps += -acc;
    }
    float mean = blk_sum<512>(ps) * (1.0f / NPIX);
    float pss = 0.f;
    for (int i = tid; i < NPIX; i += 512) {
        float d = ob[i] - mean;
        pss += d * d;
    }
    float var = blk_sum<512>(pss) * (1.0f / NPIX);
    float istd = rsqrtf(var + 1e-5f);
    float sc = istd * g1[ch], sh = b1[ch] - mean * sc;
    for (int i = tid; i < NPIX; i += 512) {
        int bb = i / HW, p = i - bb * HW;
        out[((size_t)(bb * 64 + ch)) * HW + p] = fmaxf(ob[i] * sc + sh, 0.0f);
    }
}

// ---------------- final: bn3/bnds from sums + residual add + relu + KL -----
__global__ void __launch_bounds__(256) final_kernel(
    const float* __restrict__ g3, const float* __restrict__ b3,
    const float* __restrict__ gds, const float* __restrict__ bds,
    float* __restrict__ out, int out_size)
{
    int idx4 = blockIdx.x * 256 + threadIdx.x;
    if (idx4 == 0 && out_size > 802816) {
        const float ns[4] = {32768.f, 8192.f, 36864.f, 16384.f};
        float kl = 0.f;
        #pragma unroll
        for (int t = 0; t < 4; ++t) {
            float ef = g_s.accf[t], el = g_s.accf[4 + t], spl = g_s.accf[8 + t];
            kl += (spl / el + logf(ef) - logf(el)) / ns[t];
        }
        out[802816] = kl;
    }
    size_t base = (size_t)idx4 * 4;
    int ch = (int)((base / HW) & 255);

    double m3d = g_s.accd[640 + ch] * (1.0 / 3136.0);
    double v3d = g_s.accd[896 + ch] * (1.0 / 3136.0) - m3d * m3d;
    float m3 = (float)m3d, istd3 = rsqrtf((float)v3d + 1e-5f);
    float sc3 = istd3 * g3[ch], sh3 = b3[ch] - m3 * sc3;

    double mdd = g_s.accd[0 + ch] * (1.0 / 3136.0);
    double vdd = g_s.accd[256 + ch] * (1.0 / 3136.0) - mdd * mdd;
    float md = (float)mdd, istdd = rsqrtf((float)vdd + 1e-5f);
    float scd = istdd * gds[ch], shd = bds[ch] - md * scd;

    float4 a = *(const float4*)(g_s.buf_c3 + base);
    float4 d = *(const float4*)(g_s.buf_ds + base);
    float4 o;
    o.x = fmaxf(fmaf(a.x, sc3, sh3) + fmaxf(fmaf(d.x, scd, shd), 0.f), 0.f);
    o.y = fmaxf(fmaf(a.y, sc3, sh3) + fmaxf(fmaf(d.y, scd, shd), 0.f), 0.f);
    o.z = fmaxf(fmaf(a.z, sc3, sh3) + fmaxf(fmaf(d.z, scd, shd), 0.f), 0.f);
    o.w = fmaxf(fmaf(a.w, sc3, sh3) + fmaxf(fmaf(d.w, scd, shd), 0.f), 0.f);
    *(float4*)(out + base) = o;
}

// ---------------------------------------------------------------------------
extern "C" void kernel_launch(void* const* d_in, const int* in_sizes, int n_in,
                              void* d_out, int out_size)
{
    const float* x    = (const float*)d_in[0];
    const float* w_ds = (const float*)d_in[1];
    const float* w_c1 = (const float*)d_in[2];
    const float* w_c2 = (const float*)d_in[3];
    const float* w_c3 = (const float*)d_in[4];
    const float* a_ds = (const float*)d_in[5];
    const float* a_c1 = (const float*)d_in[6];
    const float* a_c2 = (const float*)d_in[7];
    const float* a_c3 = (const float*)d_in[8];
    const float* pegw = (const float*)d_in[9];
    const float* g1   = (const float*)d_in[10];
    const float* b1   = (const float*)d_in[11];
    const float* g2   = (const float*)d_in[12];
    const float* b2   = (const float*)d_in[13];
    const float* g3   = (const float*)d_in[14];
    const float* b3   = (const float*)d_in[15];
    const float* gds  = (const float*)d_in[16];
    const float* bds  = (const float*)d_in[17];
    const float* lds  = (const float*)d_in[18];
    const float* lc1  = (const float*)d_in[19];
    const float* lc2  = (const float*)d_in[20];
    const float* lc3  = (const float*)d_in[21];
    float* out = (float*)d_out;

    Scratch* s = nullptr;
    cudaGetSymbolAddress((void**)&s, g_s);

    // 1) zero accumulators + per-tensor weight min/max
    prep_kernel<<<4, 1024>>>(w_ds, w_c1, w_c2, w_c3);

    // 2) bin-reconstruct all weights + KL partial sums
    recon_kernel<<<92, 256>>>(w_ds, w_c1, w_c2, w_c3,
                              a_ds, a_c1, a_c2, a_c3,
                              lds, lc1, lc2, lc3);

    // 3) fused ds (y<8, +bnds stats) and c1 (y in 8..9) over x
    adder1x1_kernel<128, true, false, false><<<dim3(13, 10, 4), 256>>>(
        x, nullptr, nullptr, 0,
        nullptr, nullptr, nullptr, nullptr, nullptr, nullptr);

    // 4) PEG depthwise + bn1 stats + bn1/relu apply -> h1
    peg_fused_kernel<<<64, 512>>>(s->buf_c1, pegw, g1, b1, s->buf_h1);

    // 5) conv2 3x3 (+ bn2 stats)
    adder3x3_kernel<<<dim3(13, 4, 4), 256>>>(
        s->buf_h1, s->f_c2, s->buf_c2, s->accd + 512, s->accd + 576);

    // 6) conv3 1x1 with inline bn2+relu on input (+ bn3 stats)
    adder1x1_kernel<64, false, true, true><<<dim3(13, 8, 4), 256>>>(
        s->buf_c2, s->f_c3, s->buf_c3, 256,
        s->accd + 512, s->accd + 576, g2, b2, s->accd + 640, s->accd + 896);

    // 7) fused epilogue: bn3 + relu(bnds) residual + relu, and KL scalar
    final_kernel<<<784, 256>>>(g3, b3, gds, bds, out, out_size);
}